// round 15
// baseline (speedup 1.0000x reference)
#include <cuda_runtime.h>
#include <cuda_fp16.h>
#include <stdint.h>

#define TOK 16384
#define CDIM 768
#define NCDIM 3072
#define DFFDIM 3072

// ---------------- device scratch (static; no allocs allowed) ----------------
__device__ __half g_xh[(size_t)TOK * NCDIM];      // x in fp16
__device__ float  g_invr[TOK];
__device__ __half g_phit[32 * NCDIM];             // phi^T padded [32][3072]
__device__ __half g_w1h[(size_t)CDIM * DFFDIM];   // W1 fp16, native [768][3072]
__device__ __half g_w2h[(size_t)DFFDIM * CDIM];   // W2 fp16, native [3072][768]
__device__ float  g_hpre[TOK * 4];
__device__ float  g_hpost[TOK * 4];
__device__ float  g_hres[TOK * 16];
__device__ __half g_xinh[(size_t)TOK * CDIM];     // pre-aggregated stream, fp16
__device__ __half g_hidh[(size_t)TOK * DFFDIM];   // gelu(x_in@W1+b1), fp16

// ---- kernel 1: rms sumsq + fp32->fp16 convert + phi pad + weight convert (indep blocks) ----
#define SSBLKS 2048
#define WCBLKS 256

__global__ void sumsq_convert_kernel(const float* __restrict__ x,
                                     const float* __restrict__ phi,
                                     const float* __restrict__ W1,
                                     const float* __restrict__ W2) {
    if (blockIdx.x >= SSBLKS) {
        int i = (blockIdx.x - SSBLKS) * 256 + threadIdx.x;
        const int stride = WCBLKS * 256;
        const int WELEM4 = (CDIM * DFFDIM) / 4;
        for (int idx = i; idx < WELEM4; idx += stride) {
            float4 v = ((const float4*)W1)[idx];
            ((__half2*)g_w1h)[2 * idx]     = __floats2half2_rn(v.x, v.y);
            ((__half2*)g_w1h)[2 * idx + 1] = __floats2half2_rn(v.z, v.w);
            float4 w = ((const float4*)W2)[idx];
            ((__half2*)g_w2h)[2 * idx]     = __floats2half2_rn(w.x, w.y);
            ((__half2*)g_w2h)[2 * idx + 1] = __floats2half2_rn(w.z, w.w);
        }
        return;
    }
    int gid = blockIdx.x * blockDim.x + threadIdx.x;
    if (gid < 32 * NCDIM) {
        int j = gid / NCDIM, k = gid % NCDIM;
        g_phit[gid] = (j < 24) ? __float2half(phi[k * 24 + j]) : __float2half(0.0f);
    }
    int gw = gid >> 5;
    int lane = threadIdx.x & 31;
    if (gw >= TOK) return;
    const float4* row = (const float4*)(x + (size_t)gw * NCDIM);
    __half2* outrow = (__half2*)(g_xh + (size_t)gw * NCDIM);
    float ss = 0.f;
    #pragma unroll 4
    for (int i = lane; i < NCDIM / 4; i += 32) {
        float4 v = row[i];
        ss += v.x * v.x + v.y * v.y + v.z * v.z + v.w * v.w;
        outrow[2 * i]     = __floats2half2_rn(v.x, v.y);
        outrow[2 * i + 1] = __floats2half2_rn(v.z, v.w);
    }
    #pragma unroll
    for (int o = 16; o; o >>= 1) ss += __shfl_xor_sync(0xffffffffu, ss, o);
    if (lane == 0) g_invr[gw] = rsqrtf(ss / (float)NCDIM + 1e-6f);
}

// ---------------- cp.async helpers ----------------
#define CP_ASYNC16(dst, src) asm volatile("cp.async.cg.shared.global [%0], [%1], 16;\n" :: "r"(dst), "l"(src))
#define CP_COMMIT() asm volatile("cp.async.commit_group;\n" ::)
#define CP_WAIT(N_) asm volatile("cp.async.wait_group %0;\n" :: "n"(N_))

__device__ __forceinline__ float gelu_exact(float v) {
    return 0.5f * v * (1.0f + erff(v * 0.70710678118654752f));
}

// ============ kernel 2: fused mix GEMM (BM=64) + routing epilogue (R11-proven) ============
#define MIXBLKS 256

__global__ void __launch_bounds__(128, 2)
mix_routing_kernel(const float* __restrict__ b,  const float* __restrict__ apre,
                   const float* __restrict__ apost, const float* __restrict__ ares) {
    constexpr int BM = 64, BK = 32, BN = 32;
    constexpr int THREADS = 128;
    constexpr int K = NCDIM, KT = K / BK;
    const __half* __restrict__ A  = g_xh;
    const __half* __restrict__ Bt = g_phit;

    __shared__ alignas(16) __half sA[2][BM * BK];
    __shared__ alignas(16) __half sB[2][BN * BK];
    __shared__ float smix[64][25];
    uint32_t sAb = (uint32_t)__cvta_generic_to_shared(&sA[0][0]);
    uint32_t sBb = (uint32_t)__cvta_generic_to_shared(&sB[0][0]);

    const int tid = threadIdx.x;
    const int mBase = blockIdx.x * BM;

    auto loadTiles = [&](int stg, int kt) {
        int k0 = kt * BK;
        #pragma unroll
        for (int it = 0; it < 2; it++) {
            int ch = tid + it * THREADS;
            int row = ch >> 2, k8 = ch & 3;
            const __half* g = A + (size_t)(mBase + row) * K + k0 + k8 * 8;
            uint32_t d = sAb + 2 * (stg * BM * BK + row * BK + ((k8 ^ ((row >> 1) & 3)) << 3));
            CP_ASYNC16(d, g);
        }
        {
            int ch = tid;
            int row = ch >> 2, k8 = ch & 3;
            const __half* g = Bt + (size_t)row * K + k0 + k8 * 8;
            uint32_t d = sBb + 2 * (stg * BN * BK + row * BK + ((k8 ^ ((row >> 1) & 3)) << 3));
            CP_ASYNC16(d, g);
        }
    };

    const int warp = tid >> 5, lane = tid & 31;
    float acc[4][4];
    #pragma unroll
    for (int j = 0; j < 4; j++)
        #pragma unroll
        for (int q = 0; q < 4; q++) acc[j][q] = 0.f;

    const int aRow = lane & 15, aKc = lane >> 4;
    const int bRow = lane & 7,  bKc = (lane >> 3) & 1;

    loadTiles(0, 0);
    CP_COMMIT();
    for (int kt = 0; kt < KT; kt++) {
        int cur = kt & 1;
        if (kt + 1 < KT) { loadTiles(cur ^ 1, kt + 1); CP_COMMIT(); CP_WAIT(1); }
        else             { CP_WAIT(0); }
        __syncthreads();
        #pragma unroll
        for (int ks = 0; ks < 2; ks++) {
            uint32_t a[4], bfr[4][2];
            {
                int row = warp * 16 + aRow;
                int k8 = ks * 2 + aKc;
                uint32_t ad = sAb + 2 * (cur * BM * BK + row * BK + ((k8 ^ ((row >> 1) & 3)) << 3));
                asm volatile("ldmatrix.sync.aligned.m8n8.x4.shared.b16 {%0,%1,%2,%3}, [%4];\n"
                             : "=r"(a[0]), "=r"(a[1]), "=r"(a[2]), "=r"(a[3]) : "r"(ad));
            }
            #pragma unroll
            for (int fn = 0; fn < 4; fn++) {
                int row = fn * 8 + bRow;
                int k8 = ks * 2 + bKc;
                uint32_t bd = sBb + 2 * (cur * BN * BK + row * BK + ((k8 ^ ((row >> 1) & 3)) << 3));
                asm volatile("ldmatrix.sync.aligned.m8n8.x2.shared.b16 {%0,%1}, [%2];\n"
                             : "=r"(bfr[fn][0]), "=r"(bfr[fn][1]) : "r"(bd));
            }
            #pragma unroll
            for (int fn = 0; fn < 4; fn++)
                asm volatile(
                    "mma.sync.aligned.m16n8k16.row.col.f32.f16.f16.f32 "
                    "{%0,%1,%2,%3}, {%4,%5,%6,%7}, {%8,%9}, {%0,%1,%2,%3};\n"
                    : "+f"(acc[fn][0]), "+f"(acc[fn][1]), "+f"(acc[fn][2]), "+f"(acc[fn][3])
                    : "r"(a[0]), "r"(a[1]), "r"(a[2]), "r"(a[3]),
                      "r"(bfr[fn][0]), "r"(bfr[fn][1]));
        }
        __syncthreads();
    }

    const int gq = lane >> 2, cq = lane & 3;
    {
        int rl0 = warp * 16 + gq, rl1 = rl0 + 8;
        #pragma unroll
        for (int fn = 0; fn < 3; fn++) {
            int c0 = fn * 8 + cq * 2;
            smix[rl0][c0] = acc[fn][0]; smix[rl0][c0 + 1] = acc[fn][1];
            smix[rl1][c0] = acc[fn][2]; smix[rl1][c0 + 1] = acc[fn][3];
        }
    }
    __syncthreads();

    if (tid < 64) {
        int t = mBase + tid;
        float invr = g_invr[t];
        float m[24];
        #pragma unroll
        for (int i = 0; i < 24; i++) m[i] = smix[tid][i] * invr;
        float ap = apre[0], apo = apost[0], ar = ares[0];
        #pragma unroll
        for (int n = 0; n < 4; n++)
            g_hpre[t * 4 + n] = __fdividef(1.0f, 1.0f + __expf(-(m[n] * ap + b[n])));
        #pragma unroll
        for (int n = 0; n < 4; n++)
            g_hpost[t * 4 + n] = __fdividef(2.0f, 1.0f + __expf(-(m[4 + n] * apo + b[4 + n])));
        float r[16];
        #pragma unroll
        for (int i = 0; i < 16; i++) r[i] = m[8 + i] * ar + b[8 + i];
        #pragma unroll
        for (int row = 0; row < 4; row++) {
            float mx = r[row * 4];
            #pragma unroll
            for (int j = 1; j < 4; j++) mx = fmaxf(mx, r[row * 4 + j]);
            #pragma unroll
            for (int j = 0; j < 4; j++) r[row * 4 + j] = __expf(r[row * 4 + j] - mx);
        }
        for (int it = 0; it < 20; it++) {
            #pragma unroll
            for (int row = 0; row < 4; row++) {
                float inv = __fdividef(1.0f, r[row * 4] + r[row * 4 + 1] + r[row * 4 + 2] + r[row * 4 + 3] + 1e-6f);
                #pragma unroll
                for (int j = 0; j < 4; j++) r[row * 4 + j] *= inv;
            }
            #pragma unroll
            for (int col = 0; col < 4; col++) {
                float inv = __fdividef(1.0f, r[col] + r[4 + col] + r[8 + col] + r[12 + col] + 1e-6f);
                #pragma unroll
                for (int row = 0; row < 4; row++) r[row * 4 + col] *= inv;
            }
        }
        #pragma unroll
        for (int i = 0; i < 16; i++) g_hres[t * 16 + i] = r[i];
    }
}

// ---------------- kernel 3: x_in = sum_n h_pre[n] * x[n,:] (R11-proven) ----------------
__global__ void xin_kernel() {
    int idx = blockIdx.x * blockDim.x + threadIdx.x;
    if (idx >= TOK * 384) return;
    int t = idx / 384, c2 = idx % 384;
    const __half2* xh2 = (const __half2*)g_xh;
    float ax = 0.f, ay = 0.f;
    #pragma unroll
    for (int n = 0; n < 4; n++) {
        float2 v = __half22float2(xh2[(size_t)t * 1536 + n * 384 + c2]);
        float h = g_hpre[t * 4 + n];
        ax += h * v.x; ay += h * v.y;
    }
    ((__half2*)g_xinh)[(size_t)t * 384 + c2] = __floats2half2_rn(ax, ay);
}

// ================= big GEMM: BM=128, BN=256, BK=64, 3-stage, trans-B =================
// R15 change: BN 128->256, 8 warps (2x4), each warp keeps the R11-proven 64x64 shape.
// Halves A-operand L2 re-reads (grid.x halved) and doubles warps/SM for latency cover.
// B smem tile: 64 k-rows x 256 n-cols = 512B rows (32 chunks), swizzle c^(row&7) unchanged.
#define HP_STAGES 3
#define HP_A_BYTES 16384                       // A: 128 x 64 fp16
#define HP_B_BYTES 32768                       // B: 64 x 256 fp16
#define HP_STG_BYTES (HP_A_BYTES + HP_B_BYTES) // 49152 per stage
#define HP_THREADS 256
#define HP_BN 256

template <int KDIM, int EPI>
__global__ void __launch_bounds__(HP_THREADS, 1)
gemm_hp(const float* __restrict__ bias, float* __restrict__ out) {
    constexpr int BM = 128, BK = 64;
    constexpr int KT = KDIM / BK;
    constexpr int WN = (EPI == 1) ? DFFDIM : CDIM;   // weight row length (n-dim)

    const __half* __restrict__ A  = (EPI == 1) ? g_xinh : g_hidh;
    const __half* __restrict__ Bw = (EPI == 1) ? g_w1h  : g_w2h;

    extern __shared__ char smem_raw[];
    uint32_t sAb = (uint32_t)__cvta_generic_to_shared(smem_raw);

    const int tid = threadIdx.x, warp = tid >> 5, lane = tid & 31;
    const int mBase = blockIdx.y * BM;
    const int nBase = blockIdx.x * HP_BN;
    const int wm = warp >> 2, wn = warp & 3;     // 2x4 warps, each 64x64

    auto loadTiles = [&](int stg, int kt) {
        int k0 = kt * BK;
        uint32_t sb = sAb + stg * HP_STG_BYTES;
        #pragma unroll
        for (int it = 0; it < 4; it++) {          // A: 128 rows x 8 chunks (128B rows)
            int ch = tid + it * HP_THREADS;
            int row = ch >> 3, c = ch & 7;
            const __half* g = A + (size_t)(mBase + row) * KDIM + k0 + c * 8;
            CP_ASYNC16(sb + row * 128 + ((c ^ (row & 7)) << 4), g);
        }
        #pragma unroll
        for (int it = 0; it < 8; it++) {          // B: 64 k-rows x 32 chunks (512B rows)
            int ch = tid + it * HP_THREADS;
            int row = ch >> 5, c = ch & 31;
            const __half* g = Bw + (size_t)(k0 + row) * WN + nBase + c * 8;
            CP_ASYNC16(sb + HP_A_BYTES + row * 512 + ((c ^ (row & 7)) << 4), g);
        }
    };

    const int aRow = lane & 15, aKc = lane >> 4;

    float acc[4][8][4];
    #pragma unroll
    for (int i = 0; i < 4; i++)
        #pragma unroll
        for (int j = 0; j < 8; j++)
            #pragma unroll
            for (int q = 0; q < 4; q++) acc[i][j][q] = 0.f;

    loadTiles(0, 0); CP_COMMIT();
    loadTiles(1, 1); CP_COMMIT();

    for (int kt = 0; kt < KT; kt++) {
        int cur = kt % 3;
        if (kt + 2 < KT) { loadTiles((kt + 2) % 3, kt + 2); CP_COMMIT(); CP_WAIT(2); }
        else             { CP_WAIT(0); }
        __syncthreads();

        uint32_t sb = sAb + cur * HP_STG_BYTES;
        #pragma unroll
        for (int ks = 0; ks < 4; ks++) {
            uint32_t a[4][4], b[8][2];
            #pragma unroll
            for (int fm = 0; fm < 4; fm++) {
                int row = wm * 64 + fm * 16 + aRow;
                int c = ks * 2 + aKc;
                uint32_t ad = sb + row * 128 + ((c ^ (row & 7)) << 4);
                asm volatile("ldmatrix.sync.aligned.m8n8.x4.shared.b16 {%0,%1,%2,%3}, [%4];\n"
                             : "=r"(a[fm][0]), "=r"(a[fm][1]), "=r"(a[fm][2]), "=r"(a[fm][3])
                             : "r"(ad));
            }
            {
                int krow = ks * 16 + (lane & 15);
                #pragma unroll
                for (int fn = 0; fn < 8; fn++) {
                    int chunkN = (wn * 64 + fn * 8) >> 3;        // 16B chunk along n (0..31)
                    uint32_t bd = sb + HP_A_BYTES + krow * 512 + ((chunkN ^ (krow & 7)) << 4);
                    asm volatile("ldmatrix.sync.aligned.m8n8.x2.trans.shared.b16 {%0,%1}, [%2];\n"
                                 : "=r"(b[fn][0]), "=r"(b[fn][1])
                                 : "r"(bd));
                }
            }
            #pragma unroll
            for (int fm = 0; fm < 4; fm++)
                #pragma unroll
                for (int fn = 0; fn < 8; fn++)
                    asm volatile(
                        "mma.sync.aligned.m16n8k16.row.col.f32.f16.f16.f32 "
                        "{%0,%1,%2,%3}, {%4,%5,%6,%7}, {%8,%9}, {%0,%1,%2,%3};\n"
                        : "+f"(acc[fm][fn][0]), "+f"(acc[fm][fn][1]),
                          "+f"(acc[fm][fn][2]), "+f"(acc[fm][fn][3])
                        : "r"(a[fm][0]), "r"(a[fm][1]), "r"(a[fm][2]), "r"(a[fm][3]),
                          "r"(b[fn][0]), "r"(b[fn][1]));
        }
        __syncthreads();
    }

    // ---------------- epilogues (R11-verbatim math; nBase stride 256) ----------------
    const int gq = lane >> 2, cq = lane & 3;
    if constexpr (EPI == 1) {
        #pragma unroll
        for (int fm = 0; fm < 4; fm++)
            #pragma unroll
            for (int fn = 0; fn < 8; fn++) {
                int r0 = mBase + wm * 64 + fm * 16 + gq;
                int c0 = nBase + wn * 64 + fn * 8 + cq * 2;
                float bz0 = bias[c0], bz1 = bias[c0 + 1];
                float v0 = gelu_exact(acc[fm][fn][0] + bz0);
                float v1 = gelu_exact(acc[fm][fn][1] + bz1);
                float v2 = gelu_exact(acc[fm][fn][2] + bz0);
                float v3 = gelu_exact(acc[fm][fn][3] + bz1);
                __half2* o = (__half2*)g_hidh;
                o[((size_t)r0 * DFFDIM + c0) >> 1]       = __floats2half2_rn(v0, v1);
                o[((size_t)(r0 + 8) * DFFDIM + c0) >> 1] = __floats2half2_rn(v2, v3);
            }
    } else {
        #pragma unroll
        for (int fm = 0; fm < 4; fm++) {
            int r0 = mBase + wm * 64 + fm * 16 + gq;
            int r1 = r0 + 8;
            float hp0[4], hp1[4], hr0[16], hr1[16];
            #pragma unroll
            for (int n = 0; n < 4; n++) { hp0[n] = g_hpost[r0 * 4 + n]; hp1[n] = g_hpost[r1 * 4 + n]; }
            #pragma unroll
            for (int i = 0; i < 16; i++) { hr0[i] = g_hres[r0 * 16 + i]; hr1[i] = g_hres[r1 * 16 + i]; }
            #pragma unroll
            for (int fn = 0; fn < 8; fn++) {
                int c0 = nBase + wn * 64 + fn * 8 + cq * 2;
                float bz0 = bias[c0], bz1 = bias[c0 + 1];
                float f0x = acc[fm][fn][0] + bz0, f0y = acc[fm][fn][1] + bz1;
                float f1x = acc[fm][fn][2] + bz0, f1y = acc[fm][fn][3] + bz1;
                float2 x0[4], x1[4];
                #pragma unroll
                for (int j = 0; j < 4; j++) {
                    x0[j] = __half22float2(*(const __half2*)(g_xh + (size_t)r0 * NCDIM + j * CDIM + c0));
                    x1[j] = __half22float2(*(const __half2*)(g_xh + (size_t)r1 * NCDIM + j * CDIM + c0));
                }
                #pragma unroll
                for (int n = 0; n < 4; n++) {
                    float ox = hp0[n] * f0x, oy = hp0[n] * f0y;
                    #pragma unroll
                    for (int j = 0; j < 4; j++) {
                        ox += hr0[n * 4 + j] * x0[j].x;
                        oy += hr0[n * 4 + j] * x0[j].y;
                    }
                    *(float2*)(out + ((size_t)r0 * 4 + n) * CDIM + c0) = make_float2(ox, oy);
                }
                #pragma unroll
                for (int n = 0; n < 4; n++) {
                    float ox = hp1[n] * f1x, oy = hp1[n] * f1y;
                    #pragma unroll
                    for (int j = 0; j < 4; j++) {
                        ox += hr1[n * 4 + j] * x1[j].x;
                        oy += hr1[n * 4 + j] * x1[j].y;
                    }
                    *(float2*)(out + ((size_t)r1 * 4 + n) * CDIM + c0) = make_float2(ox, oy);
                }
            }
        }
    }
}

// ---------------- launch ----------------
extern "C" void kernel_launch(void* const* d_in, const int* in_sizes, int n_in,
                              void* d_out, int out_size) {
    const float* x     = (const float*)d_in[0];
    const float* phi   = (const float*)d_in[1];
    const float* b     = (const float*)d_in[2];
    const float* apre  = (const float*)d_in[3];
    const float* apost = (const float*)d_in[4];
    const float* ares  = (const float*)d_in[5];
    const float* W1    = (const float*)d_in[6];
    const float* b1    = (const float*)d_in[7];
    const float* W2    = (const float*)d_in[8];
    const float* b2    = (const float*)d_in[9];
    float* out = (float*)d_out;

    const int dyn_smem = HP_STAGES * HP_STG_BYTES;   // 144 KB
    cudaFuncSetAttribute(gemm_hp<CDIM, 1>,  cudaFuncAttributeMaxDynamicSharedMemorySize, dyn_smem);
    cudaFuncSetAttribute(gemm_hp<NCDIM, 2>, cudaFuncAttributeMaxDynamicSharedMemorySize, dyn_smem);

    sumsq_convert_kernel<<<SSBLKS + WCBLKS, 256>>>(x, phi, W1, W2);
    mix_routing_kernel<<<MIXBLKS, 128>>>(b, apre, apost, ares);
    xin_kernel<<<TOK * 384 / 256, 256>>>();
    gemm_hp<CDIM, 1><<<dim3(DFFDIM / HP_BN, TOK / 128), HP_THREADS, dyn_smem>>>(b1, nullptr);
    gemm_hp<NCDIM, 2><<<dim3(CDIM / HP_BN, TOK / 128), HP_THREADS, dyn_smem>>>(b2, out);
}

// round 16
// speedup vs baseline: 1.1018x; 1.1018x over previous
#include <cuda_runtime.h>
#include <cuda_fp16.h>
#include <stdint.h>

#define TOK 16384
#define CDIM 768
#define NCDIM 3072
#define DFFDIM 3072

// ---------------- device scratch (static; no allocs allowed) ----------------
__device__ __half g_xh[(size_t)TOK * NCDIM];      // x in fp16
__device__ float  g_invr[TOK];
__device__ __half g_phit[32 * NCDIM];             // phi^T padded [32][3072]
__device__ __half g_w1h[(size_t)CDIM * DFFDIM];   // W1 fp16, native [768][3072]
__device__ __half g_w2h[(size_t)DFFDIM * CDIM];   // W2 fp16, native [3072][768]
__device__ float  g_hpre[TOK * 4];
__device__ float  g_hpost[TOK * 4];
__device__ float  g_hres[TOK * 16];
__device__ __half g_xinh[(size_t)TOK * CDIM];     // pre-aggregated stream, fp16
__device__ __half g_hidh[(size_t)TOK * DFFDIM];   // gelu(x_in@W1+b1), fp16

// ---- kernel 1: rms sumsq + fp32->fp16 convert + phi pad + weight convert (indep blocks) ----
#define SSBLKS 2048
#define WCBLKS 256

__global__ void sumsq_convert_kernel(const float* __restrict__ x,
                                     const float* __restrict__ phi,
                                     const float* __restrict__ W1,
                                     const float* __restrict__ W2) {
    if (blockIdx.x >= SSBLKS) {
        int i = (blockIdx.x - SSBLKS) * 256 + threadIdx.x;
        const int stride = WCBLKS * 256;
        const int WELEM4 = (CDIM * DFFDIM) / 4;
        for (int idx = i; idx < WELEM4; idx += stride) {
            float4 v = ((const float4*)W1)[idx];
            ((__half2*)g_w1h)[2 * idx]     = __floats2half2_rn(v.x, v.y);
            ((__half2*)g_w1h)[2 * idx + 1] = __floats2half2_rn(v.z, v.w);
            float4 w = ((const float4*)W2)[idx];
            ((__half2*)g_w2h)[2 * idx]     = __floats2half2_rn(w.x, w.y);
            ((__half2*)g_w2h)[2 * idx + 1] = __floats2half2_rn(w.z, w.w);
        }
        return;
    }
    int gid = blockIdx.x * blockDim.x + threadIdx.x;
    if (gid < 32 * NCDIM) {
        int j = gid / NCDIM, k = gid % NCDIM;
        g_phit[gid] = (j < 24) ? __float2half(phi[k * 24 + j]) : __float2half(0.0f);
    }
    int gw = gid >> 5;
    int lane = threadIdx.x & 31;
    if (gw >= TOK) return;
    const float4* row = (const float4*)(x + (size_t)gw * NCDIM);
    __half2* outrow = (__half2*)(g_xh + (size_t)gw * NCDIM);
    float ss = 0.f;
    #pragma unroll 4
    for (int i = lane; i < NCDIM / 4; i += 32) {
        float4 v = row[i];
        ss += v.x * v.x + v.y * v.y + v.z * v.z + v.w * v.w;
        outrow[2 * i]     = __floats2half2_rn(v.x, v.y);
        outrow[2 * i + 1] = __floats2half2_rn(v.z, v.w);
    }
    #pragma unroll
    for (int o = 16; o; o >>= 1) ss += __shfl_xor_sync(0xffffffffu, ss, o);
    if (lane == 0) g_invr[gw] = rsqrtf(ss / (float)NCDIM + 1e-6f);
}

// ---------------- cp.async helpers ----------------
#define CP_ASYNC16(dst, src) asm volatile("cp.async.cg.shared.global [%0], [%1], 16;\n" :: "r"(dst), "l"(src))
#define CP_COMMIT() asm volatile("cp.async.commit_group;\n" ::)
#define CP_WAIT(N_) asm volatile("cp.async.wait_group %0;\n" :: "n"(N_))

__device__ __forceinline__ float gelu_exact(float v) {
    return 0.5f * v * (1.0f + erff(v * 0.70710678118654752f));
}

// ============ kernel 2: fused mix GEMM (BM=64) + routing epilogue (R11-proven) ============
#define MIXBLKS 256

__global__ void __launch_bounds__(128, 2)
mix_routing_kernel(const float* __restrict__ b,  const float* __restrict__ apre,
                   const float* __restrict__ apost, const float* __restrict__ ares) {
    constexpr int BM = 64, BK = 32, BN = 32;
    constexpr int THREADS = 128;
    constexpr int K = NCDIM, KT = K / BK;
    const __half* __restrict__ A  = g_xh;
    const __half* __restrict__ Bt = g_phit;

    __shared__ alignas(16) __half sA[2][BM * BK];
    __shared__ alignas(16) __half sB[2][BN * BK];
    __shared__ float smix[64][25];
    uint32_t sAb = (uint32_t)__cvta_generic_to_shared(&sA[0][0]);
    uint32_t sBb = (uint32_t)__cvta_generic_to_shared(&sB[0][0]);

    const int tid = threadIdx.x;
    const int mBase = blockIdx.x * BM;

    auto loadTiles = [&](int stg, int kt) {
        int k0 = kt * BK;
        #pragma unroll
        for (int it = 0; it < 2; it++) {
            int ch = tid + it * THREADS;
            int row = ch >> 2, k8 = ch & 3;
            const __half* g = A + (size_t)(mBase + row) * K + k0 + k8 * 8;
            uint32_t d = sAb + 2 * (stg * BM * BK + row * BK + ((k8 ^ ((row >> 1) & 3)) << 3));
            CP_ASYNC16(d, g);
        }
        {
            int ch = tid;
            int row = ch >> 2, k8 = ch & 3;
            const __half* g = Bt + (size_t)row * K + k0 + k8 * 8;
            uint32_t d = sBb + 2 * (stg * BN * BK + row * BK + ((k8 ^ ((row >> 1) & 3)) << 3));
            CP_ASYNC16(d, g);
        }
    };

    const int warp = tid >> 5, lane = tid & 31;
    float acc[4][4];
    #pragma unroll
    for (int j = 0; j < 4; j++)
        #pragma unroll
        for (int q = 0; q < 4; q++) acc[j][q] = 0.f;

    const int aRow = lane & 15, aKc = lane >> 4;
    const int bRow = lane & 7,  bKc = (lane >> 3) & 1;

    loadTiles(0, 0);
    CP_COMMIT();
    for (int kt = 0; kt < KT; kt++) {
        int cur = kt & 1;
        if (kt + 1 < KT) { loadTiles(cur ^ 1, kt + 1); CP_COMMIT(); CP_WAIT(1); }
        else             { CP_WAIT(0); }
        __syncthreads();
        #pragma unroll
        for (int ks = 0; ks < 2; ks++) {
            uint32_t a[4], bfr[4][2];
            {
                int row = warp * 16 + aRow;
                int k8 = ks * 2 + aKc;
                uint32_t ad = sAb + 2 * (cur * BM * BK + row * BK + ((k8 ^ ((row >> 1) & 3)) << 3));
                asm volatile("ldmatrix.sync.aligned.m8n8.x4.shared.b16 {%0,%1,%2,%3}, [%4];\n"
                             : "=r"(a[0]), "=r"(a[1]), "=r"(a[2]), "=r"(a[3]) : "r"(ad));
            }
            #pragma unroll
            for (int fn = 0; fn < 4; fn++) {
                int row = fn * 8 + bRow;
                int k8 = ks * 2 + bKc;
                uint32_t bd = sBb + 2 * (cur * BN * BK + row * BK + ((k8 ^ ((row >> 1) & 3)) << 3));
                asm volatile("ldmatrix.sync.aligned.m8n8.x2.shared.b16 {%0,%1}, [%2];\n"
                             : "=r"(bfr[fn][0]), "=r"(bfr[fn][1]) : "r"(bd));
            }
            #pragma unroll
            for (int fn = 0; fn < 4; fn++)
                asm volatile(
                    "mma.sync.aligned.m16n8k16.row.col.f32.f16.f16.f32 "
                    "{%0,%1,%2,%3}, {%4,%5,%6,%7}, {%8,%9}, {%0,%1,%2,%3};\n"
                    : "+f"(acc[fn][0]), "+f"(acc[fn][1]), "+f"(acc[fn][2]), "+f"(acc[fn][3])
                    : "r"(a[0]), "r"(a[1]), "r"(a[2]), "r"(a[3]),
                      "r"(bfr[fn][0]), "r"(bfr[fn][1]));
        }
        __syncthreads();
    }

    const int gq = lane >> 2, cq = lane & 3;
    {
        int rl0 = warp * 16 + gq, rl1 = rl0 + 8;
        #pragma unroll
        for (int fn = 0; fn < 3; fn++) {
            int c0 = fn * 8 + cq * 2;
            smix[rl0][c0] = acc[fn][0]; smix[rl0][c0 + 1] = acc[fn][1];
            smix[rl1][c0] = acc[fn][2]; smix[rl1][c0 + 1] = acc[fn][3];
        }
    }
    __syncthreads();

    if (tid < 64) {
        int t = mBase + tid;
        float invr = g_invr[t];
        float m[24];
        #pragma unroll
        for (int i = 0; i < 24; i++) m[i] = smix[tid][i] * invr;
        float ap = apre[0], apo = apost[0], ar = ares[0];
        #pragma unroll
        for (int n = 0; n < 4; n++)
            g_hpre[t * 4 + n] = __fdividef(1.0f, 1.0f + __expf(-(m[n] * ap + b[n])));
        #pragma unroll
        for (int n = 0; n < 4; n++)
            g_hpost[t * 4 + n] = __fdividef(2.0f, 1.0f + __expf(-(m[4 + n] * apo + b[4 + n])));
        float r[16];
        #pragma unroll
        for (int i = 0; i < 16; i++) r[i] = m[8 + i] * ar + b[8 + i];
        #pragma unroll
        for (int row = 0; row < 4; row++) {
            float mx = r[row * 4];
            #pragma unroll
            for (int j = 1; j < 4; j++) mx = fmaxf(mx, r[row * 4 + j]);
            #pragma unroll
            for (int j = 0; j < 4; j++) r[row * 4 + j] = __expf(r[row * 4 + j] - mx);
        }
        for (int it = 0; it < 20; it++) {
            #pragma unroll
            for (int row = 0; row < 4; row++) {
                float inv = __fdividef(1.0f, r[row * 4] + r[row * 4 + 1] + r[row * 4 + 2] + r[row * 4 + 3] + 1e-6f);
                #pragma unroll
                for (int j = 0; j < 4; j++) r[row * 4 + j] *= inv;
            }
            #pragma unroll
            for (int col = 0; col < 4; col++) {
                float inv = __fdividef(1.0f, r[col] + r[4 + col] + r[8 + col] + r[12 + col] + 1e-6f);
                #pragma unroll
                for (int row = 0; row < 4; row++) r[row * 4 + col] *= inv;
            }
        }
        #pragma unroll
        for (int i = 0; i < 16; i++) g_hres[t * 16 + i] = r[i];
    }
}

// ---------------- kernel 3: x_in = sum_n h_pre[n] * x[n,:] (R11-proven) ----------------
__global__ void xin_kernel() {
    int idx = blockIdx.x * blockDim.x + threadIdx.x;
    if (idx >= TOK * 384) return;
    int t = idx / 384, c2 = idx % 384;
    const __half2* xh2 = (const __half2*)g_xh;
    float ax = 0.f, ay = 0.f;
    #pragma unroll
    for (int n = 0; n < 4; n++) {
        float2 v = __half22float2(xh2[(size_t)t * 1536 + n * 384 + c2]);
        float h = g_hpre[t * 4 + n];
        ax += h * v.x; ay += h * v.y;
    }
    ((__half2*)g_xinh)[(size_t)t * 384 + c2] = __floats2half2_rn(ax, ay);
}

// ================= big GEMM: BM=128, BN=128, BK=64, 3-stage, trans-B =================
// R16 change vs R11/R14: single-barrier mainloop. Loads for stage (kt+2) are issued
// AFTER the top barrier of iteration kt; the top barrier of kt+1 guarantees all warps
// finished compute of kt before stage kt%3 is overwritten at kt+1 (writes (kt+3)%3=kt%3).
// Wait bookkeeping: at iter kt, committed groups {0..kt+1}; CP_WAIT(1) => group kt done.
// Last iteration uses CP_WAIT(0).
#define HP_STAGES 3
#define HP_STG_BYTES (256 * 64 * 2)   // A(128x64) 16KB + B(64x128) 16KB per stage
#define HP_THREADS 128

template <int KDIM, int EPI>
__global__ void __launch_bounds__(HP_THREADS, 2)
gemm_hp(const float* __restrict__ bias, float* __restrict__ out) {
    constexpr int BM = 128, BK = 64;
    constexpr int KT = KDIM / BK;
    constexpr int WN = (EPI == 1) ? DFFDIM : CDIM;   // weight row length (n-dim)

    const __half* __restrict__ A  = (EPI == 1) ? g_xinh : g_hidh;
    const __half* __restrict__ Bw = (EPI == 1) ? g_w1h  : g_w2h;

    extern __shared__ char smem_raw[];
    uint32_t sAb = (uint32_t)__cvta_generic_to_shared(smem_raw);

    const int tid = threadIdx.x, warp = tid >> 5, lane = tid & 31;
    const int mBase = blockIdx.y * BM;
    const int nBase = blockIdx.x * 128;
    const int wm = warp >> 1, wn = warp & 1;     // 2x2 warps, each 64x64

    auto loadTiles = [&](int stg, int kt) {
        int k0 = kt * BK;
        uint32_t sb = sAb + stg * HP_STG_BYTES;
        #pragma unroll
        for (int it = 0; it < 8; it++) {          // A: 128 rows x 8 chunks (128B rows)
            int ch = tid + it * HP_THREADS;
            int row = ch >> 3, c = ch & 7;
            const __half* g = A + (size_t)(mBase + row) * KDIM + k0 + c * 8;
            CP_ASYNC16(sb + row * 128 + ((c ^ (row & 7)) << 4), g);
        }
        #pragma unroll
        for (int it = 0; it < 8; it++) {          // B: 64 k-rows x 16 chunks (256B rows)
            int ch = tid + it * HP_THREADS;
            int row = ch >> 4, c = ch & 15;
            const __half* g = Bw + (size_t)(k0 + row) * WN + nBase + c * 8;
            CP_ASYNC16(sb + 16384 + row * 256 + ((c ^ (row & 7)) << 4), g);
        }
    };

    const int aRow = lane & 15, aKc = lane >> 4;

    float acc[4][8][4];
    #pragma unroll
    for (int i = 0; i < 4; i++)
        #pragma unroll
        for (int j = 0; j < 8; j++)
            #pragma unroll
            for (int q = 0; q < 4; q++) acc[i][j][q] = 0.f;

    loadTiles(0, 0); CP_COMMIT();
    loadTiles(1, 1); CP_COMMIT();

    for (int kt = 0; kt < KT; kt++) {
        int cur = kt % 3;
        if (kt + 1 < KT) { CP_WAIT(1); }          // groups <= kt complete
        else             { CP_WAIT(0); }
        __syncthreads();                          // stage cur visible + prev compute done
        if (kt + 2 < KT) { loadTiles((kt + 2) % 3, kt + 2); CP_COMMIT(); }

        uint32_t sb = sAb + cur * HP_STG_BYTES;
        #pragma unroll
        for (int ks = 0; ks < 4; ks++) {
            uint32_t a[4][4], b[8][2];
            #pragma unroll
            for (int fm = 0; fm < 4; fm++) {
                int row = wm * 64 + fm * 16 + aRow;
                int c = ks * 2 + aKc;
                uint32_t ad = sb + row * 128 + ((c ^ (row & 7)) << 4);
                asm volatile("ldmatrix.sync.aligned.m8n8.x4.shared.b16 {%0,%1,%2,%3}, [%4];\n"
                             : "=r"(a[fm][0]), "=r"(a[fm][1]), "=r"(a[fm][2]), "=r"(a[fm][3])
                             : "r"(ad));
            }
            {
                int krow = ks * 16 + (lane & 15);
                #pragma unroll
                for (int fn = 0; fn < 8; fn++) {
                    int chunkN = (wn * 64 + fn * 8) >> 3;        // 16B chunk along n
                    uint32_t bd = sb + 16384 + krow * 256 + ((chunkN ^ (krow & 7)) << 4);
                    asm volatile("ldmatrix.sync.aligned.m8n8.x2.trans.shared.b16 {%0,%1}, [%2];\n"
                                 : "=r"(b[fn][0]), "=r"(b[fn][1])
                                 : "r"(bd));
                }
            }
            #pragma unroll
            for (int fm = 0; fm < 4; fm++)
                #pragma unroll
                for (int fn = 0; fn < 8; fn++)
                    asm volatile(
                        "mma.sync.aligned.m16n8k16.row.col.f32.f16.f16.f32 "
                        "{%0,%1,%2,%3}, {%4,%5,%6,%7}, {%8,%9}, {%0,%1,%2,%3};\n"
                        : "+f"(acc[fm][fn][0]), "+f"(acc[fm][fn][1]),
                          "+f"(acc[fm][fn][2]), "+f"(acc[fm][fn][3])
                        : "r"(a[fm][0]), "r"(a[fm][1]), "r"(a[fm][2]), "r"(a[fm][3]),
                          "r"(b[fn][0]), "r"(b[fn][1]));
        }
        // no trailing barrier: next iteration's top barrier protects stage reuse
    }

    // ---------------- epilogues (R11-verbatim) ----------------
    const int gq = lane >> 2, cq = lane & 3;
    if constexpr (EPI == 1) {
        #pragma unroll
        for (int fm = 0; fm < 4; fm++)
            #pragma unroll
            for (int fn = 0; fn < 8; fn++) {
                int r0 = mBase + wm * 64 + fm * 16 + gq;
                int c0 = nBase + wn * 64 + fn * 8 + cq * 2;
                float bz0 = bias[c0], bz1 = bias[c0 + 1];
                float v0 = gelu_exact(acc[fm][fn][0] + bz0);
                float v1 = gelu_exact(acc[fm][fn][1] + bz1);
                float v2 = gelu_exact(acc[fm][fn][2] + bz0);
                float v3 = gelu_exact(acc[fm][fn][3] + bz1);
                __half2* o = (__half2*)g_hidh;
                o[((size_t)r0 * DFFDIM + c0) >> 1]       = __floats2half2_rn(v0, v1);
                o[((size_t)(r0 + 8) * DFFDIM + c0) >> 1] = __floats2half2_rn(v2, v3);
            }
    } else {
        #pragma unroll
        for (int fm = 0; fm < 4; fm++) {
            int r0 = mBase + wm * 64 + fm * 16 + gq;
            int r1 = r0 + 8;
            float hp0[4], hp1[4], hr0[16], hr1[16];
            #pragma unroll
            for (int n = 0; n < 4; n++) { hp0[n] = g_hpost[r0 * 4 + n]; hp1[n] = g_hpost[r1 * 4 + n]; }
            #pragma unroll
            for (int i = 0; i < 16; i++) { hr0[i] = g_hres[r0 * 16 + i]; hr1[i] = g_hres[r1 * 16 + i]; }
            #pragma unroll
            for (int fn = 0; fn < 8; fn++) {
                int c0 = nBase + wn * 64 + fn * 8 + cq * 2;
                float bz0 = bias[c0], bz1 = bias[c0 + 1];
                float f0x = acc[fm][fn][0] + bz0, f0y = acc[fm][fn][1] + bz1;
                float f1x = acc[fm][fn][2] + bz0, f1y = acc[fm][fn][3] + bz1;
                float2 x0[4], x1[4];
                #pragma unroll
                for (int j = 0; j < 4; j++) {
                    x0[j] = __half22float2(*(const __half2*)(g_xh + (size_t)r0 * NCDIM + j * CDIM + c0));
                    x1[j] = __half22float2(*(const __half2*)(g_xh + (size_t)r1 * NCDIM + j * CDIM + c0));
                }
                #pragma unroll
                for (int n = 0; n < 4; n++) {
                    float ox = hp0[n] * f0x, oy = hp0[n] * f0y;
                    #pragma unroll
                    for (int j = 0; j < 4; j++) {
                        ox += hr0[n * 4 + j] * x0[j].x;
                        oy += hr0[n * 4 + j] * x0[j].y;
                    }
                    *(float2*)(out + ((size_t)r0 * 4 + n) * CDIM + c0) = make_float2(ox, oy);
                }
                #pragma unroll
                for (int n = 0; n < 4; n++) {
                    float ox = hp1[n] * f1x, oy = hp1[n] * f1y;
                    #pragma unroll
                    for (int j = 0; j < 4; j++) {
                        ox += hr1[n * 4 + j] * x1[j].x;
                        oy += hr1[n * 4 + j] * x1[j].y;
                    }
                    *(float2*)(out + ((size_t)r1 * 4 + n) * CDIM + c0) = make_float2(ox, oy);
                }
            }
        }
    }
}

// ---------------- launch ----------------
extern "C" void kernel_launch(void* const* d_in, const int* in_sizes, int n_in,
                              void* d_out, int out_size) {
    const float* x     = (const float*)d_in[0];
    const float* phi   = (const float*)d_in[1];
    const float* b     = (const float*)d_in[2];
    const float* apre  = (const float*)d_in[3];
    const float* apost = (const float*)d_in[4];
    const float* ares  = (const float*)d_in[5];
    const float* W1    = (const float*)d_in[6];
    const float* b1    = (const float*)d_in[7];
    const float* W2    = (const float*)d_in[8];
    const float* b2    = (const float*)d_in[9];
    float* out = (float*)d_out;

    const int dyn_smem = HP_STAGES * HP_STG_BYTES;   // 96 KB
    cudaFuncSetAttribute(gemm_hp<CDIM, 1>,  cudaFuncAttributeMaxDynamicSharedMemorySize, dyn_smem);
    cudaFuncSetAttribute(gemm_hp<NCDIM, 2>, cudaFuncAttributeMaxDynamicSharedMemorySize, dyn_smem);

    sumsq_convert_kernel<<<SSBLKS + WCBLKS, 256>>>(x, phi, W1, W2);
    mix_routing_kernel<<<MIXBLKS, 128>>>(b, apre, apost, ares);
    xin_kernel<<<TOK * 384 / 256, 256>>>();
    gemm_hp<CDIM, 1><<<dim3(DFFDIM / 128, TOK / 128), HP_THREADS, dyn_smem>>>(b1, nullptr);
    gemm_hp<NCDIM, 2><<<dim3(CDIM / 128, TOK / 128), HP_THREADS, dyn_smem>>>(b2, out);
}

// round 17
// speedup vs baseline: 1.1365x; 1.0315x over previous
#include <cuda_runtime.h>
#include <cuda_fp16.h>
#include <stdint.h>

#define TOK 16384
#define CDIM 768
#define NCDIM 3072
#define DFFDIM 3072

// ---------------- device scratch (static; no allocs allowed) ----------------
__device__ __half g_xh[(size_t)TOK * NCDIM];      // x in fp16
__device__ float  g_invr[TOK];
__device__ __half g_phit[32 * NCDIM];             // phi^T padded [32][3072]
__device__ __half g_w1h[(size_t)CDIM * DFFDIM];   // W1 fp16, native [768][3072]
__device__ __half g_w2h[(size_t)DFFDIM * CDIM];   // W2 fp16, native [3072][768]
__device__ float  g_hpre[TOK * 4];
__device__ float  g_hpost[TOK * 4];
__device__ float  g_hres[TOK * 16];
__device__ __half g_xinh[(size_t)TOK * CDIM];     // pre-aggregated stream, fp16
__device__ __half g_hidh[(size_t)TOK * DFFDIM];   // gelu(x_in@W1+b1), fp16

// ---- kernel 1: rms sumsq + fp32->fp16 convert + phi pad + weight convert (indep blocks) ----
#define SSBLKS 2048
#define WCBLKS 256

__global__ void sumsq_convert_kernel(const float* __restrict__ x,
                                     const float* __restrict__ phi,
                                     const float* __restrict__ W1,
                                     const float* __restrict__ W2) {
    if (blockIdx.x >= SSBLKS) {
        int i = (blockIdx.x - SSBLKS) * 256 + threadIdx.x;
        const int stride = WCBLKS * 256;
        const int WELEM4 = (CDIM * DFFDIM) / 4;
        for (int idx = i; idx < WELEM4; idx += stride) {
            float4 v = ((const float4*)W1)[idx];
            ((__half2*)g_w1h)[2 * idx]     = __floats2half2_rn(v.x, v.y);
            ((__half2*)g_w1h)[2 * idx + 1] = __floats2half2_rn(v.z, v.w);
            float4 w = ((const float4*)W2)[idx];
            ((__half2*)g_w2h)[2 * idx]     = __floats2half2_rn(w.x, w.y);
            ((__half2*)g_w2h)[2 * idx + 1] = __floats2half2_rn(w.z, w.w);
        }
        return;
    }
    int gid = blockIdx.x * blockDim.x + threadIdx.x;
    if (gid < 32 * NCDIM) {
        int j = gid / NCDIM, k = gid % NCDIM;
        g_phit[gid] = (j < 24) ? __float2half(phi[k * 24 + j]) : __float2half(0.0f);
    }
    int gw = gid >> 5;
    int lane = threadIdx.x & 31;
    if (gw >= TOK) return;
    const float4* row = (const float4*)(x + (size_t)gw * NCDIM);
    __half2* outrow = (__half2*)(g_xh + (size_t)gw * NCDIM);
    float ss = 0.f;
    #pragma unroll 4
    for (int i = lane; i < NCDIM / 4; i += 32) {
        float4 v = row[i];
        ss += v.x * v.x + v.y * v.y + v.z * v.z + v.w * v.w;
        outrow[2 * i]     = __floats2half2_rn(v.x, v.y);
        outrow[2 * i + 1] = __floats2half2_rn(v.z, v.w);
    }
    #pragma unroll
    for (int o = 16; o; o >>= 1) ss += __shfl_xor_sync(0xffffffffu, ss, o);
    if (lane == 0) g_invr[gw] = rsqrtf(ss / (float)NCDIM + 1e-6f);
}

// ---------------- cp.async helpers ----------------
#define CP_ASYNC16(dst, src) asm volatile("cp.async.cg.shared.global [%0], [%1], 16;\n" :: "r"(dst), "l"(src))
#define CP_COMMIT() asm volatile("cp.async.commit_group;\n" ::)
#define CP_WAIT(N_) asm volatile("cp.async.wait_group %0;\n" :: "n"(N_))

__device__ __forceinline__ float gelu_exact(float v) {
    return 0.5f * v * (1.0f + erff(v * 0.70710678118654752f));
}

// ============ kernel 2: fused mix GEMM (BM=64) + routing epilogue (R11-proven) ============
#define MIXBLKS 256

__global__ void __launch_bounds__(128, 2)
mix_routing_kernel(const float* __restrict__ b,  const float* __restrict__ apre,
                   const float* __restrict__ apost, const float* __restrict__ ares) {
    constexpr int BM = 64, BK = 32, BN = 32;
    constexpr int THREADS = 128;
    constexpr int K = NCDIM, KT = K / BK;
    const __half* __restrict__ A  = g_xh;
    const __half* __restrict__ Bt = g_phit;

    __shared__ alignas(16) __half sA[2][BM * BK];
    __shared__ alignas(16) __half sB[2][BN * BK];
    __shared__ float smix[64][25];
    uint32_t sAb = (uint32_t)__cvta_generic_to_shared(&sA[0][0]);
    uint32_t sBb = (uint32_t)__cvta_generic_to_shared(&sB[0][0]);

    const int tid = threadIdx.x;
    const int mBase = blockIdx.x * BM;

    auto loadTiles = [&](int stg, int kt) {
        int k0 = kt * BK;
        #pragma unroll
        for (int it = 0; it < 2; it++) {
            int ch = tid + it * THREADS;
            int row = ch >> 2, k8 = ch & 3;
            const __half* g = A + (size_t)(mBase + row) * K + k0 + k8 * 8;
            uint32_t d = sAb + 2 * (stg * BM * BK + row * BK + ((k8 ^ ((row >> 1) & 3)) << 3));
            CP_ASYNC16(d, g);
        }
        {
            int ch = tid;
            int row = ch >> 2, k8 = ch & 3;
            const __half* g = Bt + (size_t)row * K + k0 + k8 * 8;
            uint32_t d = sBb + 2 * (stg * BN * BK + row * BK + ((k8 ^ ((row >> 1) & 3)) << 3));
            CP_ASYNC16(d, g);
        }
    };

    const int warp = tid >> 5, lane = tid & 31;
    float acc[4][4];
    #pragma unroll
    for (int j = 0; j < 4; j++)
        #pragma unroll
        for (int q = 0; q < 4; q++) acc[j][q] = 0.f;

    const int aRow = lane & 15, aKc = lane >> 4;
    const int bRow = lane & 7,  bKc = (lane >> 3) & 1;

    loadTiles(0, 0);
    CP_COMMIT();
    for (int kt = 0; kt < KT; kt++) {
        int cur = kt & 1;
        if (kt + 1 < KT) { loadTiles(cur ^ 1, kt + 1); CP_COMMIT(); CP_WAIT(1); }
        else             { CP_WAIT(0); }
        __syncthreads();
        #pragma unroll
        for (int ks = 0; ks < 2; ks++) {
            uint32_t a[4], bfr[4][2];
            {
                int row = warp * 16 + aRow;
                int k8 = ks * 2 + aKc;
                uint32_t ad = sAb + 2 * (cur * BM * BK + row * BK + ((k8 ^ ((row >> 1) & 3)) << 3));
                asm volatile("ldmatrix.sync.aligned.m8n8.x4.shared.b16 {%0,%1,%2,%3}, [%4];\n"
                             : "=r"(a[0]), "=r"(a[1]), "=r"(a[2]), "=r"(a[3]) : "r"(ad));
            }
            #pragma unroll
            for (int fn = 0; fn < 4; fn++) {
                int row = fn * 8 + bRow;
                int k8 = ks * 2 + bKc;
                uint32_t bd = sBb + 2 * (cur * BN * BK + row * BK + ((k8 ^ ((row >> 1) & 3)) << 3));
                asm volatile("ldmatrix.sync.aligned.m8n8.x2.shared.b16 {%0,%1}, [%2];\n"
                             : "=r"(bfr[fn][0]), "=r"(bfr[fn][1]) : "r"(bd));
            }
            #pragma unroll
            for (int fn = 0; fn < 4; fn++)
                asm volatile(
                    "mma.sync.aligned.m16n8k16.row.col.f32.f16.f16.f32 "
                    "{%0,%1,%2,%3}, {%4,%5,%6,%7}, {%8,%9}, {%0,%1,%2,%3};\n"
                    : "+f"(acc[fn][0]), "+f"(acc[fn][1]), "+f"(acc[fn][2]), "+f"(acc[fn][3])
                    : "r"(a[0]), "r"(a[1]), "r"(a[2]), "r"(a[3]),
                      "r"(bfr[fn][0]), "r"(bfr[fn][1]));
        }
        __syncthreads();
    }

    const int gq = lane >> 2, cq = lane & 3;
    {
        int rl0 = warp * 16 + gq, rl1 = rl0 + 8;
        #pragma unroll
        for (int fn = 0; fn < 3; fn++) {
            int c0 = fn * 8 + cq * 2;
            smix[rl0][c0] = acc[fn][0]; smix[rl0][c0 + 1] = acc[fn][1];
            smix[rl1][c0] = acc[fn][2]; smix[rl1][c0 + 1] = acc[fn][3];
        }
    }
    __syncthreads();

    if (tid < 64) {
        int t = mBase + tid;
        float invr = g_invr[t];
        float m[24];
        #pragma unroll
        for (int i = 0; i < 24; i++) m[i] = smix[tid][i] * invr;
        float ap = apre[0], apo = apost[0], ar = ares[0];
        #pragma unroll
        for (int n = 0; n < 4; n++)
            g_hpre[t * 4 + n] = __fdividef(1.0f, 1.0f + __expf(-(m[n] * ap + b[n])));
        #pragma unroll
        for (int n = 0; n < 4; n++)
            g_hpost[t * 4 + n] = __fdividef(2.0f, 1.0f + __expf(-(m[4 + n] * apo + b[4 + n])));
        float r[16];
        #pragma unroll
        for (int i = 0; i < 16; i++) r[i] = m[8 + i] * ar + b[8 + i];
        #pragma unroll
        for (int row = 0; row < 4; row++) {
            float mx = r[row * 4];
            #pragma unroll
            for (int j = 1; j < 4; j++) mx = fmaxf(mx, r[row * 4 + j]);
            #pragma unroll
            for (int j = 0; j < 4; j++) r[row * 4 + j] = __expf(r[row * 4 + j] - mx);
        }
        for (int it = 0; it < 20; it++) {
            #pragma unroll
            for (int row = 0; row < 4; row++) {
                float inv = __fdividef(1.0f, r[row * 4] + r[row * 4 + 1] + r[row * 4 + 2] + r[row * 4 + 3] + 1e-6f);
                #pragma unroll
                for (int j = 0; j < 4; j++) r[row * 4 + j] *= inv;
            }
            #pragma unroll
            for (int col = 0; col < 4; col++) {
                float inv = __fdividef(1.0f, r[col] + r[4 + col] + r[8 + col] + r[12 + col] + 1e-6f);
                #pragma unroll
                for (int row = 0; row < 4; row++) r[row * 4 + col] *= inv;
            }
        }
        #pragma unroll
        for (int i = 0; i < 16; i++) g_hres[t * 16 + i] = r[i];
    }
}

// ---------------- kernel 3: x_in = sum_n h_pre[n] * x[n,:] (R11-proven) ----------------
__global__ void xin_kernel() {
    int idx = blockIdx.x * blockDim.x + threadIdx.x;
    if (idx >= TOK * 384) return;
    int t = idx / 384, c2 = idx % 384;
    const __half2* xh2 = (const __half2*)g_xh;
    float ax = 0.f, ay = 0.f;
    #pragma unroll
    for (int n = 0; n < 4; n++) {
        float2 v = __half22float2(xh2[(size_t)t * 1536 + n * 384 + c2]);
        float h = g_hpre[t * 4 + n];
        ax += h * v.x; ay += h * v.y;
    }
    ((__half2*)g_xinh)[(size_t)t * 384 + c2] = __floats2half2_rn(ax, ay);
}

// ================= big GEMM: BM=128, BN=128, BK=64, 3-stage, trans-B =================
// R17 change vs R14: smem-staged epilogues. After the (unchanged) mainloop, acc
// fragments (+bias) are staged to a padded fp32 smem tile f_s[128][132]; then a
// warp-per-token pass re-reads it so that ALL global traffic (hid stores, x reads,
// out stores) is fully coalesced (8-16B per lane, contiguous per warp).
#define HP_STAGES 3
#define HP_STG_BYTES (256 * 64 * 2)   // A(128x64) 16KB + B(64x128) 16KB per stage
#define HP_THREADS 128
#define FSTRIDE 132                    // fp32 row stride for staging tile (padded)

template <int KDIM, int EPI>
__global__ void __launch_bounds__(HP_THREADS, 2)
gemm_hp(const float* __restrict__ bias, float* __restrict__ out) {
    constexpr int BM = 128, BK = 64;
    constexpr int KT = KDIM / BK;
    constexpr int WN = (EPI == 1) ? DFFDIM : CDIM;   // weight row length (n-dim)

    const __half* __restrict__ A  = (EPI == 1) ? g_xinh : g_hidh;
    const __half* __restrict__ Bw = (EPI == 1) ? g_w1h  : g_w2h;

    extern __shared__ char smem_raw[];
    uint32_t sAb = (uint32_t)__cvta_generic_to_shared(smem_raw);

    const int tid = threadIdx.x, warp = tid >> 5, lane = tid & 31;
    const int mBase = blockIdx.y * BM;
    const int nBase = blockIdx.x * 128;
    const int wm = warp >> 1, wn = warp & 1;     // 2x2 warps, each 64x64

    auto loadTiles = [&](int stg, int kt) {
        int k0 = kt * BK;
        uint32_t sb = sAb + stg * HP_STG_BYTES;
        #pragma unroll
        for (int it = 0; it < 8; it++) {          // A: 128 rows x 8 chunks (128B rows)
            int ch = tid + it * HP_THREADS;
            int row = ch >> 3, c = ch & 7;
            const __half* g = A + (size_t)(mBase + row) * KDIM + k0 + c * 8;
            CP_ASYNC16(sb + row * 128 + ((c ^ (row & 7)) << 4), g);
        }
        #pragma unroll
        for (int it = 0; it < 8; it++) {          // B: 64 k-rows x 16 chunks (256B rows)
            int ch = tid + it * HP_THREADS;
            int row = ch >> 4, c = ch & 15;
            const __half* g = Bw + (size_t)(k0 + row) * WN + nBase + c * 8;
            CP_ASYNC16(sb + 16384 + row * 256 + ((c ^ (row & 7)) << 4), g);
        }
    };

    const int aRow = lane & 15, aKc = lane >> 4;

    float acc[4][8][4];
    #pragma unroll
    for (int i = 0; i < 4; i++)
        #pragma unroll
        for (int j = 0; j < 8; j++)
            #pragma unroll
            for (int q = 0; q < 4; q++) acc[i][j][q] = 0.f;

    loadTiles(0, 0); CP_COMMIT();
    loadTiles(1, 1); CP_COMMIT();

    for (int kt = 0; kt < KT; kt++) {
        int cur = kt % 3;
        if (kt + 2 < KT) { loadTiles((kt + 2) % 3, kt + 2); CP_COMMIT(); CP_WAIT(2); }
        else             { CP_WAIT(0); }
        __syncthreads();

        uint32_t sb = sAb + cur * HP_STG_BYTES;
        #pragma unroll
        for (int ks = 0; ks < 4; ks++) {
            uint32_t a[4][4], b[8][2];
            #pragma unroll
            for (int fm = 0; fm < 4; fm++) {
                int row = wm * 64 + fm * 16 + aRow;
                int c = ks * 2 + aKc;
                uint32_t ad = sb + row * 128 + ((c ^ (row & 7)) << 4);
                asm volatile("ldmatrix.sync.aligned.m8n8.x4.shared.b16 {%0,%1,%2,%3}, [%4];\n"
                             : "=r"(a[fm][0]), "=r"(a[fm][1]), "=r"(a[fm][2]), "=r"(a[fm][3])
                             : "r"(ad));
            }
            {
                int krow = ks * 16 + (lane & 15);
                #pragma unroll
                for (int fn = 0; fn < 8; fn++) {
                    int chunkN = (wn * 64 + fn * 8) >> 3;        // 16B chunk along n
                    uint32_t bd = sb + 16384 + krow * 256 + ((chunkN ^ (krow & 7)) << 4);
                    asm volatile("ldmatrix.sync.aligned.m8n8.x2.trans.shared.b16 {%0,%1}, [%2];\n"
                                 : "=r"(b[fn][0]), "=r"(b[fn][1])
                                 : "r"(bd));
                }
            }
            #pragma unroll
            for (int fm = 0; fm < 4; fm++)
                #pragma unroll
                for (int fn = 0; fn < 8; fn++)
                    asm volatile(
                        "mma.sync.aligned.m16n8k16.row.col.f32.f16.f16.f32 "
                        "{%0,%1,%2,%3}, {%4,%5,%6,%7}, {%8,%9}, {%0,%1,%2,%3};\n"
                        : "+f"(acc[fm][fn][0]), "+f"(acc[fm][fn][1]),
                          "+f"(acc[fm][fn][2]), "+f"(acc[fm][fn][3])
                        : "r"(a[fm][0]), "r"(a[fm][1]), "r"(a[fm][2]), "r"(a[fm][3]),
                          "r"(b[fn][0]), "r"(b[fn][1]));
        }
        __syncthreads();
    }

    // ---------------- Phase A: stage acc (+bias) to smem f_s[128][FSTRIDE] ----------------
    float* f_s = (float*)smem_raw;   // 128*132*4 = 67584 B <= 96KB dyn smem; stages dead
    {
        const int gq = lane >> 2, cq = lane & 3;
        #pragma unroll
        for (int fm = 0; fm < 4; fm++) {
            int rl0 = wm * 64 + fm * 16 + gq;
            int rl1 = rl0 + 8;
            #pragma unroll
            for (int fn = 0; fn < 8; fn++) {
                int cl = wn * 64 + fn * 8 + cq * 2;
                float bz0 = bias[nBase + cl], bz1 = bias[nBase + cl + 1];
                f_s[rl0 * FSTRIDE + cl]     = acc[fm][fn][0] + bz0;
                f_s[rl0 * FSTRIDE + cl + 1] = acc[fm][fn][1] + bz1;
                f_s[rl1 * FSTRIDE + cl]     = acc[fm][fn][2] + bz0;
                f_s[rl1 * FSTRIDE + cl + 1] = acc[fm][fn][3] + bz1;
            }
        }
    }
    __syncthreads();

    // ---------------- Phase B: warp-per-token coalesced writeback ----------------
    if constexpr (EPI == 1) {
        #pragma unroll 1
        for (int it = 0; it < 32; it++) {
            int tt = warp * 32 + it;
            int t = mBase + tt;
            float4 fv = *(float4*)(f_s + tt * FSTRIDE + lane * 4);
            __half2 h0 = __floats2half2_rn(gelu_exact(fv.x), gelu_exact(fv.y));
            __half2 h1 = __floats2half2_rn(gelu_exact(fv.z), gelu_exact(fv.w));
            uint2 pk;
            pk.x = *(uint32_t*)&h0;
            pk.y = *(uint32_t*)&h1;
            *(uint2*)(g_hidh + (size_t)t * DFFDIM + nBase + lane * 4) = pk;
        }
    } else {
        #pragma unroll 1
        for (int it = 0; it < 32; it++) {
            int tt = warp * 32 + it;
            int t = mBase + tt;
            float4 fv = *(float4*)(f_s + tt * FSTRIDE + lane * 4);
            float hp[4], hr[16];
            #pragma unroll
            for (int n = 0; n < 4; n++) hp[n] = g_hpost[t * 4 + n];
            #pragma unroll
            for (int i = 0; i < 16; i++) hr[i] = g_hres[t * 16 + i];
            // x[j][0..3] for this lane's 4 columns
            float2 xv[4][2];
            #pragma unroll
            for (int j = 0; j < 4; j++) {
                uint2 raw = *(const uint2*)(g_xh + (size_t)t * NCDIM + j * CDIM + nBase + lane * 4);
                xv[j][0] = __half22float2(*(__half2*)&raw.x);
                xv[j][1] = __half22float2(*(__half2*)&raw.y);
            }
            #pragma unroll
            for (int n = 0; n < 4; n++) {
                float4 o;
                o.x = hp[n] * fv.x; o.y = hp[n] * fv.y;
                o.z = hp[n] * fv.z; o.w = hp[n] * fv.w;
                #pragma unroll
                for (int j = 0; j < 4; j++) {
                    float w = hr[n * 4 + j];
                    o.x += w * xv[j][0].x; o.y += w * xv[j][0].y;
                    o.z += w * xv[j][1].x; o.w += w * xv[j][1].y;
                }
                *(float4*)(out + ((size_t)t * 4 + n) * CDIM + nBase + lane * 4) = o;
            }
        }
    }
}

// ---------------- launch ----------------
extern "C" void kernel_launch(void* const* d_in, const int* in_sizes, int n_in,
                              void* d_out, int out_size) {
    const float* x     = (const float*)d_in[0];
    const float* phi   = (const float*)d_in[1];
    const float* b     = (const float*)d_in[2];
    const float* apre  = (const float*)d_in[3];
    const float* apost = (const float*)d_in[4];
    const float* ares  = (const float*)d_in[5];
    const float* W1    = (const float*)d_in[6];
    const float* b1    = (const float*)d_in[7];
    const float* W2    = (const float*)d_in[8];
    const float* b2    = (const float*)d_in[9];
    float* out = (float*)d_out;

    const int dyn_smem = HP_STAGES * HP_STG_BYTES;   // 96 KB (>= 67.6 KB staging tile)
    cudaFuncSetAttribute(gemm_hp<CDIM, 1>,  cudaFuncAttributeMaxDynamicSharedMemorySize, dyn_smem);
    cudaFuncSetAttribute(gemm_hp<NCDIM, 2>, cudaFuncAttributeMaxDynamicSharedMemorySize, dyn_smem);

    sumsq_convert_kernel<<<SSBLKS + WCBLKS, 256>>>(x, phi, W1, W2);
    mix_routing_kernel<<<MIXBLKS, 128>>>(b, apre, apost, ares);
    xin_kernel<<<TOK * 384 / 256, 256>>>();
    gemm_hp<CDIM, 1><<<dim3(DFFDIM / 128, TOK / 128), HP_THREADS, dyn_smem>>>(b1, nullptr);
    gemm_hp<NCDIM, 2><<<dim3(CDIM / 128, TOK / 128), HP_THREADS, dyn_smem>>>(b2, out);
}